// round 14
// baseline (speedup 1.0000x reference)
#include <cuda_runtime.h>
#include <cstdint>

#define NN     6144
#define INSZ   1024
#define HID    256

// ---------------- scratch (static device allocations are allowed) -----------
__device__ float  g_h[(size_t)NN * HID];     // h = X @ W           (6 MB)
__device__ float4 g_combo[NN];               // {s2, e^{s2}, e^{0.2 s2}, 0}
__device__ float4 g_rowp[NN];                // {s1, e^{s1}, e^{0.2 s1}, 0}

// ---------------- packed fp32x2 FMA (sm_103a dual-rate path) ----------------
__device__ __forceinline__ float2 fma2(float2 a, float2 b, float2 c) {
    float2 d;
    asm("fma.rn.f32x2 %0, %1, %2, %3;"
        : "=l"(reinterpret_cast<unsigned long long&>(d))
        : "l"(reinterpret_cast<unsigned long long&>(a)),
          "l"(reinterpret_cast<unsigned long long&>(b)),
          "l"(reinterpret_cast<unsigned long long&>(c)));
    return d;
}

// ============================================================================
// Kernel 1: h = X @ W   (M=6144, K=1024, N=256)  BM=128 BN=64 BK=16, 256 thr
// ============================================================================
__global__ void __launch_bounds__(256)
gemm_h_kernel(const float* __restrict__ X, const float* __restrict__ W) {
    __shared__ float As[16][128];   // k-major for vector LDS
    __shared__ float Bs[16][64];

    const int tid = threadIdx.x;
    const int i0 = blockIdx.x * 128;
    const int j0 = blockIdx.y * 64;
    const int ty = tid >> 4;        // 0..15 -> 8 rows each
    const int tx = tid & 15;        // 0..15 -> 4 cols each

    float2 c[8][2];
#pragma unroll
    for (int r = 0; r < 8; r++) { c[r][0] = make_float2(0.f, 0.f); c[r][1] = make_float2(0.f, 0.f); }

    for (int k0 = 0; k0 < INSZ; k0 += 16) {
        // A tile: 128 rows x 16 k  (512 float4 quads, 2 per thread)
#pragma unroll
        for (int l = 0; l < 2; l++) {
            int q   = tid + l * 256;
            int row = q >> 2;
            int kq  = (q & 3) * 4;
            float4 v = *(const float4*)&X[(size_t)(i0 + row) * INSZ + k0 + kq];
            As[kq + 0][row] = v.x;
            As[kq + 1][row] = v.y;
            As[kq + 2][row] = v.z;
            As[kq + 3][row] = v.w;
        }
        // B tile: 16 k x 64 cols
        {
            int krow = tid >> 4;
            int c4   = (tid & 15) * 4;
            *(float4*)&Bs[krow][c4] = *(const float4*)&W[(size_t)(k0 + krow) * HID + j0 + c4];
        }
        __syncthreads();

#pragma unroll
        for (int kk = 0; kk < 16; kk++) {
            float4 a0 = *(const float4*)&As[kk][ty * 8];
            float4 a1 = *(const float4*)&As[kk][ty * 8 + 4];
            float4 b  = *(const float4*)&Bs[kk][tx * 4];
            float2 b01 = make_float2(b.x, b.y);
            float2 b23 = make_float2(b.z, b.w);
            float av[8] = {a0.x, a0.y, a0.z, a0.w, a1.x, a1.y, a1.z, a1.w};
#pragma unroll
            for (int r = 0; r < 8; r++) {
                float2 ar = make_float2(av[r], av[r]);
                c[r][0] = fma2(b01, ar, c[r][0]);
                c[r][1] = fma2(b23, ar, c[r][1]);
            }
        }
        __syncthreads();
    }

#pragma unroll
    for (int r = 0; r < 8; r++) {
        float4 o = make_float4(c[r][0].x, c[r][0].y, c[r][1].x, c[r][1].y);
        *(float4*)&g_h[(size_t)(i0 + ty * 8 + r) * HID + j0 + tx * 4] = o;
    }
}

// ============================================================================
// Kernel 2: per-node scores + factorized exponentials
//   s1 = h@a1, s2 = h@a2;  rowp = {s1, e^{s1}, e^{0.2 s1}, 0};
//   combo = {s2, e^{s2}, e^{0.2 s2}, 0}
// ============================================================================
__global__ void __launch_bounds__(256)
prep_kernel(const float* __restrict__ a_edge) {
    int warp = threadIdx.x >> 5;
    int lane = threadIdx.x & 31;
    int i = blockIdx.x * 8 + warp;

    const float* hrow = &g_h[(size_t)i * HID];
    float d1 = 0.f, d2 = 0.f;
#pragma unroll
    for (int k = 0; k < 8; k++) {
        int cidx = lane + 32 * k;
        float hv = hrow[cidx];
        d1 += hv * a_edge[cidx];
        d2 += hv * a_edge[HID + cidx];
    }
#pragma unroll
    for (int off = 16; off > 0; off >>= 1) {
        d1 += __shfl_down_sync(0xffffffffu, d1, off);
        d2 += __shfl_down_sync(0xffffffffu, d2, off);
    }
    if (lane == 0) {
        g_rowp[i]  = make_float4(d1, expf(d1), expf(0.2f * d1), 0.f);
        g_combo[i] = make_float4(d2, expf(d2), expf(0.2f * d2), 0.f);
    }
}

// ============================================================================
// Kernel 3: fused masked-softmax + (attn @ h)
//   4 rows per block (1536 blocks), 256 threads.
//   Per j-tile of 1024: Phase A computes q for 4 rows into smem (packed as
//   float4 per j -> one broadcast LDS.128 in Phase B); Phase B does the
//   f32x2 FMA accumulation with h float4 loads amortized across 4 rows.
// ============================================================================
#define JT 1024

__global__ void __launch_bounds__(256)
attn_kernel(const int* __restrict__ adj, float* __restrict__ out) {
    __shared__ float4 qsm[JT];     // 16 KB: {q_row0..q_row3} per j
    __shared__ float  Zsh[4];

    const int tid = threadIdx.x;
    const int i0  = blockIdx.x * 4;
    const int jg  = tid >> 6;      // 0..3  (j stride group)
    const int dq  = tid & 63;      // 0..63 (column quad)

    float s1v[4], f1p[4], f1n[4];
#pragma unroll
    for (int r = 0; r < 4; r++) {
        float4 rp = g_rowp[i0 + r];
        s1v[r] = rp.x; f1p[r] = rp.y; f1n[r] = rp.z;
    }

    float  zloc[4] = {0.f, 0.f, 0.f, 0.f};
    float2 acc[4][2];
#pragma unroll
    for (int r = 0; r < 4; r++) { acc[r][0] = make_float2(0.f, 0.f); acc[r][1] = make_float2(0.f, 0.f); }

    for (int jb = 0; jb < NN; jb += JT) {
        // ---- Phase A: q for this tile (registers only) ----
        const int jq = jb + 4 * tid;
        float4 cb[4];
#pragma unroll
        for (int k = 0; k < 4; k++) cb[k] = g_combo[jq + k];

        float qv[4][4];
#pragma unroll
        for (int r = 0; r < 4; r++) {
            int4 a4 = __ldcs((const int4*)(adj + (size_t)(i0 + r) * NN + jq));
            int av[4] = {a4.x, a4.y, a4.z, a4.w};
#pragma unroll
            for (int k = 0; k < 4; k++) {
                float sc = s1v[r] + cb[k].x;
                float q  = (sc > 0.f) ? f1p[r] * cb[k].y : f1n[r] * cb[k].z;
                q = (av[k] != 0) ? q : 0.f;
                qv[r][k] = q;
                zloc[r] += q;
            }
        }

        __syncthreads();   // previous tile's Phase B fully read qsm
#pragma unroll
        for (int k = 0; k < 4; k++)
            qsm[4 * tid + k] = make_float4(qv[0][k], qv[1][k], qv[2][k], qv[3][k]);
        __syncthreads();

        // ---- Phase B: accumulate sum_j q_j * h[j][:] ----
#pragma unroll 4
        for (int k = 0; k < JT / 4; k++) {
            int jl = jg + 4 * k;
            float4 hv = *(const float4*)&g_h[(size_t)(jb + jl) * HID + 4 * dq];
            float4 q4 = qsm[jl];
            float2 h01 = make_float2(hv.x, hv.y);
            float2 h23 = make_float2(hv.z, hv.w);
            float qa[4] = {q4.x, q4.y, q4.z, q4.w};
#pragma unroll
            for (int r = 0; r < 4; r++) {
                float2 qq = make_float2(qa[r], qa[r]);
                acc[r][0] = fma2(h01, qq, acc[r][0]);
                acc[r][1] = fma2(h23, qq, acc[r][1]);
            }
        }
    }

    // ---- deterministic Z reduction (tree in smem) ----
    __syncthreads();
    float* zr = (float*)qsm;
#pragma unroll
    for (int r = 0; r < 4; r++) zr[r * 256 + tid] = zloc[r];
    __syncthreads();
    for (int s = 128; s > 0; s >>= 1) {
        if (tid < s) {
#pragma unroll
            for (int r = 0; r < 4; r++) zr[r * 256 + tid] += zr[r * 256 + tid + s];
        }
        __syncthreads();
    }
    if (tid < 4) Zsh[tid] = zr[tid * 256];
    __syncthreads();

    // ---- merge the 4 j-groups' partial accumulators, divide, write ----
    for (int r = 0; r < 4; r++) {
        __syncthreads();
        qsm[tid] = make_float4(acc[r][0].x, acc[r][0].y, acc[r][1].x, acc[r][1].y);
        __syncthreads();
        if (tid < 64) {
            float4 a = qsm[tid];
            float4 b = qsm[tid + 64];
            float4 c = qsm[tid + 128];
            float4 d = qsm[tid + 192];
            float zi = 1.f / Zsh[r];
            float4 o = make_float4((a.x + b.x + c.x + d.x) * zi,
                                   (a.y + b.y + c.y + d.y) * zi,
                                   (a.z + b.z + c.z + d.z) * zi,
                                   (a.w + b.w + c.w + d.w) * zi);
            *(float4*)&out[(size_t)(i0 + r) * HID + 4 * tid] = o;
        }
    }
}

// ============================================================================
// launch
// ============================================================================
extern "C" void kernel_launch(void* const* d_in, const int* in_sizes, int n_in,
                              void* d_out, int out_size) {
    const float* X      = (const float*)d_in[0];   // nodes_embed [6144,1024]
    const float* W      = (const float*)d_in[1];   // W           [1024,256]
    const float* a_edge = (const float*)d_in[2];   // a_edge      [512]
    const int*   adj    = (const int*)  d_in[3];   // node_adj    [6144,6144]
    float* out = (float*)d_out;                    // [6144,256] fp32

    dim3 g1(NN / 128, HID / 64);
    gemm_h_kernel<<<g1, 256>>>(X, W);
    prep_kernel<<<NN / 8, 256>>>(a_edge);
    attn_kernel<<<NN / 4, 256>>>(adj, out);
}

// round 15
// speedup vs baseline: 1.0014x; 1.0014x over previous
#include <cuda_runtime.h>
#include <cstdint>

#define NN     6144
#define INSZ   1024
#define HID    256

// ---------------- scratch (static device allocations are allowed) -----------
__device__ float  g_h[(size_t)NN * HID];     // h = X @ W           (6 MB)
__device__ float4 g_combo[NN];               // {s2, e^{s2}, e^{0.2 s2}, 0}
__device__ float4 g_rowp[NN];                // {s1, e^{s1}, e^{0.2 s1}, 0}

// ---------------- packed fp32x2 FMA (sm_103a dual-rate path) ----------------
__device__ __forceinline__ float2 fma2(float2 a, float2 b, float2 c) {
    float2 d;
    asm("fma.rn.f32x2 %0, %1, %2, %3;"
        : "=l"(reinterpret_cast<unsigned long long&>(d))
        : "l"(reinterpret_cast<unsigned long long&>(a)),
          "l"(reinterpret_cast<unsigned long long&>(b)),
          "l"(reinterpret_cast<unsigned long long&>(c)));
    return d;
}

// ============================================================================
// Kernel 1: h = X @ W   (M=6144, K=1024, N=256)  BM=128 BN=64 BK=16, 256 thr
// ============================================================================
__global__ void __launch_bounds__(256)
gemm_h_kernel(const float* __restrict__ X, const float* __restrict__ W) {
    __shared__ float As[16][128];   // k-major for vector LDS
    __shared__ float Bs[16][64];

    const int tid = threadIdx.x;
    const int i0 = blockIdx.x * 128;
    const int j0 = blockIdx.y * 64;
    const int ty = tid >> 4;        // 0..15 -> 8 rows each
    const int tx = tid & 15;        // 0..15 -> 4 cols each

    float2 c[8][2];
#pragma unroll
    for (int r = 0; r < 8; r++) { c[r][0] = make_float2(0.f, 0.f); c[r][1] = make_float2(0.f, 0.f); }

    for (int k0 = 0; k0 < INSZ; k0 += 16) {
        // A tile: 128 rows x 16 k  (512 float4 quads, 2 per thread)
#pragma unroll
        for (int l = 0; l < 2; l++) {
            int q   = tid + l * 256;
            int row = q >> 2;
            int kq  = (q & 3) * 4;
            float4 v = *(const float4*)&X[(size_t)(i0 + row) * INSZ + k0 + kq];
            As[kq + 0][row] = v.x;
            As[kq + 1][row] = v.y;
            As[kq + 2][row] = v.z;
            As[kq + 3][row] = v.w;
        }
        // B tile: 16 k x 64 cols
        {
            int krow = tid >> 4;
            int c4   = (tid & 15) * 4;
            *(float4*)&Bs[krow][c4] = *(const float4*)&W[(size_t)(k0 + krow) * HID + j0 + c4];
        }
        __syncthreads();

#pragma unroll
        for (int kk = 0; kk < 16; kk++) {
            float4 a0 = *(const float4*)&As[kk][ty * 8];
            float4 a1 = *(const float4*)&As[kk][ty * 8 + 4];
            float4 b  = *(const float4*)&Bs[kk][tx * 4];
            float2 b01 = make_float2(b.x, b.y);
            float2 b23 = make_float2(b.z, b.w);
            float av[8] = {a0.x, a0.y, a0.z, a0.w, a1.x, a1.y, a1.z, a1.w};
#pragma unroll
            for (int r = 0; r < 8; r++) {
                float2 ar = make_float2(av[r], av[r]);
                c[r][0] = fma2(b01, ar, c[r][0]);
                c[r][1] = fma2(b23, ar, c[r][1]);
            }
        }
        __syncthreads();
    }

#pragma unroll
    for (int r = 0; r < 8; r++) {
        float4 o = make_float4(c[r][0].x, c[r][0].y, c[r][1].x, c[r][1].y);
        *(float4*)&g_h[(size_t)(i0 + ty * 8 + r) * HID + j0 + tx * 4] = o;
    }
}

// ============================================================================
// Kernel 2: per-node scores + factorized exponentials
//   s1 = h@a1, s2 = h@a2;  rowp = {s1, e^{s1}, e^{0.2 s1}, 0};
//   combo = {s2, e^{s2}, e^{0.2 s2}, 0}
// ============================================================================
__global__ void __launch_bounds__(256)
prep_kernel(const float* __restrict__ a_edge) {
    int warp = threadIdx.x >> 5;
    int lane = threadIdx.x & 31;
    int i = blockIdx.x * 8 + warp;

    const float* hrow = &g_h[(size_t)i * HID];
    float d1 = 0.f, d2 = 0.f;
#pragma unroll
    for (int k = 0; k < 8; k++) {
        int cidx = lane + 32 * k;
        float hv = hrow[cidx];
        d1 += hv * a_edge[cidx];
        d2 += hv * a_edge[HID + cidx];
    }
#pragma unroll
    for (int off = 16; off > 0; off >>= 1) {
        d1 += __shfl_down_sync(0xffffffffu, d1, off);
        d2 += __shfl_down_sync(0xffffffffu, d2, off);
    }
    if (lane == 0) {
        g_rowp[i]  = make_float4(d1, expf(d1), expf(0.2f * d1), 0.f);
        g_combo[i] = make_float4(d2, expf(d2), expf(0.2f * d2), 0.f);
    }
}

// ============================================================================
// Kernel 3: fused masked-softmax + (attn @ h)
//   4 rows per block (1536 blocks), 256 threads.
//   Per j-tile of 1024: Phase A computes q for 4 rows into smem (packed as
//   float4 per j -> one broadcast LDS.128 in Phase B); Phase B does the
//   f32x2 FMA accumulation with h float4 loads amortized across 4 rows.
// ============================================================================
#define JT 1024

__global__ void __launch_bounds__(256)
attn_kernel(const int* __restrict__ adj, float* __restrict__ out) {
    __shared__ float4 qsm[JT];     // 16 KB: {q_row0..q_row3} per j
    __shared__ float  Zsh[4];

    const int tid = threadIdx.x;
    const int i0  = blockIdx.x * 4;
    const int jg  = tid >> 6;      // 0..3  (j stride group)
    const int dq  = tid & 63;      // 0..63 (column quad)

    float s1v[4], f1p[4], f1n[4];
#pragma unroll
    for (int r = 0; r < 4; r++) {
        float4 rp = g_rowp[i0 + r];
        s1v[r] = rp.x; f1p[r] = rp.y; f1n[r] = rp.z;
    }

    float  zloc[4] = {0.f, 0.f, 0.f, 0.f};
    float2 acc[4][2];
#pragma unroll
    for (int r = 0; r < 4; r++) { acc[r][0] = make_float2(0.f, 0.f); acc[r][1] = make_float2(0.f, 0.f); }

    for (int jb = 0; jb < NN; jb += JT) {
        // ---- Phase A: q for this tile (registers only) ----
        const int jq = jb + 4 * tid;
        float4 cb[4];
#pragma unroll
        for (int k = 0; k < 4; k++) cb[k] = g_combo[jq + k];

        float qv[4][4];
#pragma unroll
        for (int r = 0; r < 4; r++) {
            int4 a4 = __ldcs((const int4*)(adj + (size_t)(i0 + r) * NN + jq));
            int av[4] = {a4.x, a4.y, a4.z, a4.w};
#pragma unroll
            for (int k = 0; k < 4; k++) {
                float sc = s1v[r] + cb[k].x;
                float q  = (sc > 0.f) ? f1p[r] * cb[k].y : f1n[r] * cb[k].z;
                q = (av[k] != 0) ? q : 0.f;
                qv[r][k] = q;
                zloc[r] += q;
            }
        }

        __syncthreads();   // previous tile's Phase B fully read qsm
#pragma unroll
        for (int k = 0; k < 4; k++)
            qsm[4 * tid + k] = make_float4(qv[0][k], qv[1][k], qv[2][k], qv[3][k]);
        __syncthreads();

        // ---- Phase B: accumulate sum_j q_j * h[j][:] ----
#pragma unroll 4
        for (int k = 0; k < JT / 4; k++) {
            int jl = jg + 4 * k;
            float4 hv = *(const float4*)&g_h[(size_t)(jb + jl) * HID + 4 * dq];
            float4 q4 = qsm[jl];
            float2 h01 = make_float2(hv.x, hv.y);
            float2 h23 = make_float2(hv.z, hv.w);
            float qa[4] = {q4.x, q4.y, q4.z, q4.w};
#pragma unroll
            for (int r = 0; r < 4; r++) {
                float2 qq = make_float2(qa[r], qa[r]);
                acc[r][0] = fma2(h01, qq, acc[r][0]);
                acc[r][1] = fma2(h23, qq, acc[r][1]);
            }
        }
    }

    // ---- deterministic Z reduction (tree in smem) ----
    __syncthreads();
    float* zr = (float*)qsm;
#pragma unroll
    for (int r = 0; r < 4; r++) zr[r * 256 + tid] = zloc[r];
    __syncthreads();
    for (int s = 128; s > 0; s >>= 1) {
        if (tid < s) {
#pragma unroll
            for (int r = 0; r < 4; r++) zr[r * 256 + tid] += zr[r * 256 + tid + s];
        }
        __syncthreads();
    }
    if (tid < 4) Zsh[tid] = zr[tid * 256];
    __syncthreads();

    // ---- merge the 4 j-groups' partial accumulators, divide, write ----
    for (int r = 0; r < 4; r++) {
        __syncthreads();
        qsm[tid] = make_float4(acc[r][0].x, acc[r][0].y, acc[r][1].x, acc[r][1].y);
        __syncthreads();
        if (tid < 64) {
            float4 a = qsm[tid];
            float4 b = qsm[tid + 64];
            float4 c = qsm[tid + 128];
            float4 d = qsm[tid + 192];
            float zi = 1.f / Zsh[r];
            float4 o = make_float4((a.x + b.x + c.x + d.x) * zi,
                                   (a.y + b.y + c.y + d.y) * zi,
                                   (a.z + b.z + c.z + d.z) * zi,
                                   (a.w + b.w + c.w + d.w) * zi);
            *(float4*)&out[(size_t)(i0 + r) * HID + 4 * tid] = o;
        }
    }
}

// ============================================================================
// launch
// ============================================================================
extern "C" void kernel_launch(void* const* d_in, const int* in_sizes, int n_in,
                              void* d_out, int out_size) {
    const float* X      = (const float*)d_in[0];   // nodes_embed [6144,1024]
    const float* W      = (const float*)d_in[1];   // W           [1024,256]
    const float* a_edge = (const float*)d_in[2];   // a_edge      [512]
    const int*   adj    = (const int*)  d_in[3];   // node_adj    [6144,6144]
    float* out = (float*)d_out;                    // [6144,256] fp32

    dim3 g1(NN / 128, HID / 64);
    gemm_h_kernel<<<g1, 256>>>(X, W);
    prep_kernel<<<NN / 8, 256>>>(a_edge);
    attn_kernel<<<NN / 4, 256>>>(adj, out);
}